// round 10
// baseline (speedup 1.0000x reference)
#include <cuda_runtime.h>
#include <cuda_fp16.h>
#include <cstdint>

#define TPB  256           // 8 warps
#define PPB  256           // points per block (32 per warp)
#define PWRP 32

__device__ __forceinline__ unsigned h2u(__half2 v) { return *reinterpret_cast<unsigned*>(&v); }
__device__ __forceinline__ __half2 u2h(unsigned v) { return *reinterpret_cast<__half2*>(&v); }

// m16n8k8 row.col f16 accum: D = A@B (C=0)
__device__ __forceinline__ void mma8(unsigned& d0, unsigned& d1,
                                     unsigned a0, unsigned a1, unsigned b) {
    const unsigned z = 0;
    asm volatile("mma.sync.aligned.m16n8k8.row.col.f16.f16.f16.f16 "
                 "{%0,%1},{%2,%3},{%4},{%5,%6};"
                 : "=r"(d0), "=r"(d1)
                 : "r"(a0), "r"(a1), "r"(b), "r"(z), "r"(z));
}
// m16n8k16 row.col f32 accum: C += A@B
__device__ __forceinline__ void mma16(float* c, unsigned a0, unsigned a1,
                                      unsigned a2, unsigned a3,
                                      unsigned b0, unsigned b1) {
    asm volatile("mma.sync.aligned.m16n8k16.row.col.f32.f16.f16.f32 "
                 "{%0,%1,%2,%3},{%4,%5,%6,%7},{%8,%9},{%0,%1,%2,%3};"
                 : "+f"(c[0]), "+f"(c[1]), "+f"(c[2]), "+f"(c[3])
                 : "r"(a0), "r"(a1), "r"(a2), "r"(a3), "r"(b0), "r"(b1));
}

__global__ __launch_bounds__(TPB)
void cubeflow_mma_kernel(const float* __restrict__ input,
                         const float* __restrict__ latent,
                         const float* __restrict__ W1,
                         const float* __restrict__ b1,
                         const float* __restrict__ W2,
                         const float* __restrict__ b2,
                         float* __restrict__ out,
                         int P, int BP)
{
    __shared__ uint4 sCon[PPB];                // 16B/point: con row, fp16 padded

    const int tid  = threadIdx.x;
    const int lane = tid & 31;
    const int warp = tid >> 5;
    const int grp  = lane >> 2;                // groupID (0..7)
    const int tg   = lane & 3;                 // thread-in-group (0..3)

    const int wp0 = blockIdx.x * PPB + warp * PWRP;   // warp's first point
    const int p   = wp0 + lane;                        // this lane's point

    // theta uniform across the warp's 32 points (P = 65536, PPB | P)
    const float theta = latent[wp0 / P] * 10.0f;

    // ---- load my point, stage con row: [x0,x1,x2,0, 1,0, 0,0] fp16 ----
    const float* ip = input + (size_t)p * 3;
    const float x0 = ip[0], x1 = ip[1], x2 = ip[2];
    sCon[warp * PWRP + lane] =
        make_uint4(h2u(__floats2half2_rn(x0, x1)),
                   h2u(__floats2half2_rn(x2, 0.0f)),     // theta col zeroed
                   h2u(__floats2half2_rn(1.0f, 0.0f)),   // bias col = 1
                   0u);

    // ---- exact fp32 outputs: eval + con (overlaps weight-frag loads) ----
    {
        reinterpret_cast<float4*>(out + BP)[p] = make_float4(x0, x1, x2, theta);
        float sn, cs;
        sincosf(theta, &sn, &cs);
        const float d0 = x0 - theta, d1 = x1, d2 = x2;
        const float f1 = 1.4f * d0 * d0 + 1.4f * d1 * d1 + 0.2f * d2 * d2 - 0.5f;
        const float a2 = d2 + 0.4f;
        const float c20 = d0 * cs + d1 * sn, c21 = d1 * cs - d0 * sn;
        const float f2v = 3.8f * c20 * c20 + 0.6f * c21 * c21 + 3.8f * a2 * a2 - 0.5f;
        const float a3 = d2 - 0.6f;
        const float c30 = d0 * cs - d1 * sn, c31 = d0 * sn + d1 * cs;
        const float f3v = 0.35f * c30 * c30 + 2.8f * c31 * c31 + 2.8f * a3 * a3 - 0.5f;
        out[p] = fminf(f1, fminf(f2v, f3v));
    }

    // ---- B1 fragments: 16 hidden tiles, lane holds (k=2tg,2tg+1, n=grp) ----
    // padded K cols: [w0,w1,w2,0, bT,0, 0,0]   bT = w3*theta + b1  (exact fp32 fold)
    unsigned b1f[16];
    #pragma unroll
    for (int t = 0; t < 16; ++t) {
        const int h = 8 * t + grp;
        const float4 w = reinterpret_cast<const float4*>(W1)[h];
        const float bT = fmaf(w.w, theta, b1[h]);
        float lo, hi;
        if      (tg == 0) { lo = w.x; hi = w.y; }
        else if (tg == 1) { lo = w.z; hi = 0.f; }
        else if (tg == 2) { lo = bT;  hi = 0.f; }
        else              { lo = 0.f; hi = 0.f; }
        b1f[t] = h2u(__floats2half2_rn(lo, hi));
    }

    // ---- B2 fragments: K=128 in 8 chunks; B[k][n]=W2[n][k], n=grp (pad n>=2 -> 0)
    unsigned b2f0[8], b2f1[8];
    #pragma unroll
    for (int u = 0; u < 8; ++u) {
        if (grp < 2) {
            const float* wr = W2 + grp * 128 + 16 * u + 2 * tg;
            b2f0[u] = h2u(__floats2half2_rn(wr[0], wr[1]));
            b2f1[u] = h2u(__floats2half2_rn(wr[8], wr[9]));
        } else {
            b2f0[u] = 0u;
            b2f1[u] = 0u;
        }
    }

    __syncwarp();

    // ---- A fragments (reused by ALL 16 MMA1 tiles): 4 LDS.32 ----
    const uint32_t* sw = reinterpret_cast<const uint32_t*>(sCon);
    const int abase = (warp * PWRP + grp) * 4 + tg;
    const unsigned a00 = sw[abase];            // subtile 0: rows grp, grp+8
    const unsigned a01 = sw[abase + 32];
    const unsigned a10 = sw[abase + 64];       // subtile 1: rows 16+grp, 24+grp
    const unsigned a11 = sw[abase + 96];

    float acc0[4] = {0.f, 0.f, 0.f, 0.f};      // probs accum, subtile 0
    float acc1[4] = {0.f, 0.f, 0.f, 0.f};      // probs accum, subtile 1
    const __half2 hz = __float2half2_rn(0.0f);

    #pragma unroll
    for (int u = 0; u < 8; ++u) {
        // MMA1: hidden tiles t=2u, 2u+1 for both 16-pt subtiles (f16 accum)
        unsigned d0, d1, e0, e1, f0, f1, g0, g1;
        mma8(d0, d1, a00, a01, b1f[2 * u]);
        mma8(e0, e1, a00, a01, b1f[2 * u + 1]);
        mma8(f0, f1, a10, a11, b1f[2 * u]);
        mma8(g0, g1, a10, a11, b1f[2 * u + 1]);

        // relu in registers
        d0 = h2u(__hmax2(u2h(d0), hz));  d1 = h2u(__hmax2(u2h(d1), hz));
        e0 = h2u(__hmax2(u2h(e0), hz));  e1 = h2u(__hmax2(u2h(e1), hz));
        f0 = h2u(__hmax2(u2h(f0), hz));  f1 = h2u(__hmax2(u2h(f1), hz));
        g0 = h2u(__hmax2(u2h(g0), hz));  g1 = h2u(__hmax2(u2h(g1), hz));

        // MMA2: C-frag of m16n8 (f16) == A-frag halves of m16n8k16 — direct feed
        mma16(acc0, d0, d1, e0, e1, b2f0[u], b2f1[u]);
        mma16(acc1, f0, f1, g0, g1, b2f0[u], b2f1[u]);
    }

    // ---- epilogue: probs live on tg==0 lanes; n = {0,1} = {c0,c1}/{c2,c3} ----
    if (tg == 0) {
        const float b20 = __ldg(b2), b21 = __ldg(b2 + 1);
        float2* prp = reinterpret_cast<float2*>(out + (size_t)5 * BP);
        const int q0 = wp0 + grp;
        prp[q0]          = make_float2(acc0[0] + b20, acc0[1] + b21);
        prp[q0 + 8]      = make_float2(acc0[2] + b20, acc0[3] + b21);
        prp[q0 + 16]     = make_float2(acc1[0] + b20, acc1[1] + b21);
        prp[q0 + 24]     = make_float2(acc1[2] + b20, acc1[3] + b21);
    }
}

extern "C" void kernel_launch(void* const* d_in, const int* in_sizes, int n_in,
                              void* d_out, int out_size)
{
    const float* input  = (const float*)d_in[0];
    const float* latent = (const float*)d_in[1];
    const float* W1     = (const float*)d_in[2];
    const float* b1     = (const float*)d_in[3];
    const float* W2     = (const float*)d_in[4];
    const float* b2     = (const float*)d_in[5];
    float*       out    = (float*)d_out;

    const int BP = in_sizes[0] / 3;     // total points (B*P)
    const int B  = in_sizes[1];
    const int P  = BP / B;
    const int blocks = BP / PPB;        // 2048

    cubeflow_mma_kernel<<<blocks, TPB>>>(input, latent, W1, b1, W2, b2,
                                         out, P, BP);
}

// round 11
// speedup vs baseline: 1.2137x; 1.2137x over previous
#include <cuda_runtime.h>
#include <cuda_fp16.h>
#include <cstdint>

#define TPB    128          // 4 warps
#define TILES  4            // 32-point tiles per warp
#define PWRP   (32 * TILES) // points per warp = 128
#define PPB    (4 * PWRP)   // points per block = 512

__device__ __forceinline__ unsigned h2u(__half2 v) { return *reinterpret_cast<unsigned*>(&v); }
__device__ __forceinline__ __half2 u2h(unsigned v) { return *reinterpret_cast<__half2*>(&v); }

// m16n8k8 row.col f16 accum: D = A@B (C=0)
__device__ __forceinline__ void mma8(unsigned& d0, unsigned& d1,
                                     unsigned a0, unsigned a1, unsigned b) {
    const unsigned z = 0;
    asm volatile("mma.sync.aligned.m16n8k8.row.col.f16.f16.f16.f16 "
                 "{%0,%1},{%2,%3},{%4},{%5,%6};"
                 : "=r"(d0), "=r"(d1)
                 : "r"(a0), "r"(a1), "r"(b), "r"(z), "r"(z));
}
// m16n8k16 row.col f32 accum: C += A@B
__device__ __forceinline__ void mma16(float* c, unsigned a0, unsigned a1,
                                      unsigned a2, unsigned a3,
                                      unsigned b0, unsigned b1) {
    asm volatile("mma.sync.aligned.m16n8k16.row.col.f32.f16.f16.f32 "
                 "{%0,%1,%2,%3},{%4,%5,%6,%7},{%8,%9},{%0,%1,%2,%3};"
                 : "+f"(c[0]), "+f"(c[1]), "+f"(c[2]), "+f"(c[3])
                 : "r"(a0), "r"(a1), "r"(a2), "r"(a3), "r"(b0), "r"(b1));
}

__global__ __launch_bounds__(TPB)
void cubeflow_mma_kernel(const float* __restrict__ input,
                         const float* __restrict__ latent,
                         const float* __restrict__ W1,
                         const float* __restrict__ b1,
                         const float* __restrict__ W2,
                         const float* __restrict__ b2,
                         float* __restrict__ out,
                         int P, int BP)
{
    __shared__ uint4 sCon[4 * 32];             // per-warp 32-point staging slice

    const int tid  = threadIdx.x;
    const int lane = tid & 31;
    const int warp = tid >> 5;
    const int grp  = lane >> 2;                // groupID (0..7)
    const int tg   = lane & 3;                 // thread-in-group (0..3)

    const int wbase = blockIdx.x * PPB + warp * PWRP;   // warp's first point

    // theta uniform across the warp's 128 points (P = 65536, PWRP | P)
    const float theta = latent[wbase / P] * 10.0f;
    float sn, cs;
    sincosf(theta, &sn, &cs);                  // ONCE per warp, not per point

    // ---- B1 fragments (built once per warp): 16 hidden tiles ----
    // padded K cols: [w0,w1,w2,0, bT,0, 0,0]   bT = w3*theta + b1 (exact fp32)
    unsigned b1f[16];
    #pragma unroll
    for (int t = 0; t < 16; ++t) {
        const int h = 8 * t + grp;
        const float4 w = reinterpret_cast<const float4*>(W1)[h];
        const float bT = fmaf(w.w, theta, b1[h]);
        float lo, hi;
        if      (tg == 0) { lo = w.x; hi = w.y; }
        else if (tg == 1) { lo = w.z; hi = 0.f; }
        else if (tg == 2) { lo = bT;  hi = 0.f; }
        else              { lo = 0.f; hi = 0.f; }
        b1f[t] = h2u(__floats2half2_rn(lo, hi));
    }

    // ---- B2 fragments (once per warp): K=128 in 8 chunks; n=grp (pad>=2 -> 0)
    unsigned b2f0[8], b2f1[8];
    #pragma unroll
    for (int u = 0; u < 8; ++u) {
        if (grp < 2) {
            const float* wr = W2 + grp * 128 + 16 * u + 2 * tg;
            b2f0[u] = h2u(__floats2half2_rn(wr[0], wr[1]));
            b2f1[u] = h2u(__floats2half2_rn(wr[8], wr[9]));
        } else {
            b2f0[u] = 0u;
            b2f1[u] = 0u;
        }
    }

    const float b20 = __ldg(b2), b21 = __ldg(b2 + 1);
    const __half2 hz = __float2half2_rn(0.0f);
    const uint32_t* sw = reinterpret_cast<const uint32_t*>(sCon);
    const int abase = (warp * 32 + grp) * 4 + tg;

    #pragma unroll 1
    for (int t = 0; t < TILES; ++t) {
        const int tp0 = wbase + t * 32;        // tile's first point
        const int p   = tp0 + lane;            // this lane's point

        // ---- load my point, stage con row: [x0,x1,x2,0, 1,0, 0,0] fp16 ----
        const float* ip = input + (size_t)p * 3;
        const float x0 = ip[0], x1 = ip[1], x2 = ip[2];
        sCon[warp * 32 + lane] =
            make_uint4(h2u(__floats2half2_rn(x0, x1)),
                       h2u(__floats2half2_rn(x2, 0.0f)),     // theta col zeroed
                       h2u(__floats2half2_rn(1.0f, 0.0f)),   // bias col = 1
                       0u);

        // ---- exact fp32 outputs: eval + con (overlaps staging latency) ----
        {
            reinterpret_cast<float4*>(out + BP)[p] = make_float4(x0, x1, x2, theta);
            const float d0 = x0 - theta, d1 = x1, d2 = x2;
            const float f1 = 1.4f * d0 * d0 + 1.4f * d1 * d1
                           + 0.2f * d2 * d2 - 0.5f;
            const float a2 = d2 + 0.4f;
            const float c20 = d0 * cs + d1 * sn, c21 = d1 * cs - d0 * sn;
            const float f2v = 3.8f * c20 * c20 + 0.6f * c21 * c21
                            + 3.8f * a2 * a2 - 0.5f;
            const float a3 = d2 - 0.6f;
            const float c30 = d0 * cs - d1 * sn, c31 = d0 * sn + d1 * cs;
            const float f3v = 0.35f * c30 * c30 + 2.8f * c31 * c31
                            + 2.8f * a3 * a3 - 0.5f;
            out[p] = fminf(f1, fminf(f2v, f3v));
        }

        __syncwarp();

        // ---- A fragments (reused by ALL 16 MMA1 tiles): 4 LDS.32 ----
        const unsigned a00 = sw[abase];            // subtile 0: rows grp, grp+8
        const unsigned a01 = sw[abase + 32];
        const unsigned a10 = sw[abase + 64];       // subtile 1: rows 16+grp, 24+grp
        const unsigned a11 = sw[abase + 96];

        __syncwarp();   // reads done before next tile overwrites the slice

        float acc0[4] = {0.f, 0.f, 0.f, 0.f};
        float acc1[4] = {0.f, 0.f, 0.f, 0.f};

        #pragma unroll
        for (int u = 0; u < 8; ++u) {
            // MMA1: hidden tiles 2u, 2u+1 for both 16-pt subtiles (f16 accum)
            unsigned d0, d1, e0, e1, f0, f1, g0, g1;
            mma8(d0, d1, a00, a01, b1f[2 * u]);
            mma8(e0, e1, a00, a01, b1f[2 * u + 1]);
            mma8(f0, f1, a10, a11, b1f[2 * u]);
            mma8(g0, g1, a10, a11, b1f[2 * u + 1]);

            // relu in registers
            d0 = h2u(__hmax2(u2h(d0), hz));  d1 = h2u(__hmax2(u2h(d1), hz));
            e0 = h2u(__hmax2(u2h(e0), hz));  e1 = h2u(__hmax2(u2h(e1), hz));
            f0 = h2u(__hmax2(u2h(f0), hz));  f1 = h2u(__hmax2(u2h(f1), hz));
            g0 = h2u(__hmax2(u2h(g0), hz));  g1 = h2u(__hmax2(u2h(g1), hz));

            // MMA2: f16 C-frag of m16n8 == A-frag halves of m16n8k16
            mma16(acc0, d0, d1, e0, e1, b2f0[u], b2f1[u]);
            mma16(acc1, f0, f1, g0, g1, b2f0[u], b2f1[u]);
        }

        // ---- epilogue: probs live on tg==0 lanes; n={0,1} ----
        if (tg == 0) {
            float2* prp = reinterpret_cast<float2*>(out + (size_t)5 * BP);
            const int q0 = tp0 + grp;
            prp[q0]      = make_float2(acc0[0] + b20, acc0[1] + b21);
            prp[q0 + 8]  = make_float2(acc0[2] + b20, acc0[3] + b21);
            prp[q0 + 16] = make_float2(acc1[0] + b20, acc1[1] + b21);
            prp[q0 + 24] = make_float2(acc1[2] + b20, acc1[3] + b21);
        }
    }
}

extern "C" void kernel_launch(void* const* d_in, const int* in_sizes, int n_in,
                              void* d_out, int out_size)
{
    const float* input  = (const float*)d_in[0];
    const float* latent = (const float*)d_in[1];
    const float* W1     = (const float*)d_in[2];
    const float* b1     = (const float*)d_in[3];
    const float* W2     = (const float*)d_in[4];
    const float* b2     = (const float*)d_in[5];
    float*       out    = (float*)d_out;

    const int BP = in_sizes[0] / 3;     // total points (B*P)
    const int B  = in_sizes[1];
    const int P  = BP / B;
    const int blocks = BP / PPB;        // 1024

    cubeflow_mma_kernel<<<blocks, TPB>>>(input, latent, W1, b1, W2, b2,
                                         out, P, BP);
}

// round 12
// speedup vs baseline: 1.2280x; 1.0118x over previous
#include <cuda_runtime.h>
#include <cuda_fp16.h>
#include <cstdint>

#define TPB    256          // 8 warps
#define TILES  2            // 32-point tiles per warp
#define PWRP   (32 * TILES) // points per warp = 64
#define PPB    (8 * PWRP)   // points per block = 512

__device__ __forceinline__ unsigned h2u(__half2 v) { return *reinterpret_cast<unsigned*>(&v); }
__device__ __forceinline__ __half2 u2h(unsigned v) { return *reinterpret_cast<__half2*>(&v); }

// m16n8k8 row.col f16 accum: D = A@B (C=0)
__device__ __forceinline__ void mma8(unsigned& d0, unsigned& d1,
                                     unsigned a0, unsigned a1, unsigned b) {
    const unsigned z = 0;
    asm volatile("mma.sync.aligned.m16n8k8.row.col.f16.f16.f16.f16 "
                 "{%0,%1},{%2,%3},{%4},{%5,%6};"
                 : "=r"(d0), "=r"(d1)
                 : "r"(a0), "r"(a1), "r"(b), "r"(z), "r"(z));
}
// m16n8k16 row.col f32 accum: C += A@B
__device__ __forceinline__ void mma16(float* c, unsigned a0, unsigned a1,
                                      unsigned a2, unsigned a3,
                                      unsigned b0, unsigned b1) {
    asm volatile("mma.sync.aligned.m16n8k16.row.col.f32.f16.f16.f32 "
                 "{%0,%1,%2,%3},{%4,%5,%6,%7},{%8,%9},{%0,%1,%2,%3};"
                 : "+f"(c[0]), "+f"(c[1]), "+f"(c[2]), "+f"(c[3])
                 : "r"(a0), "r"(a1), "r"(a2), "r"(a3), "r"(b0), "r"(b1));
}

__global__ __launch_bounds__(TPB, 4)   // cap at 64 regs -> 32 warps/SM resident
void cubeflow_mma_kernel(const float* __restrict__ input,
                         const float* __restrict__ latent,
                         const float* __restrict__ W1,
                         const float* __restrict__ b1,
                         const float* __restrict__ W2,
                         const float* __restrict__ b2,
                         float* __restrict__ out,
                         int P, int BP)
{
    __shared__ uint4 sCon[8 * 32];             // per-warp 32-point staging slice

    const int tid  = threadIdx.x;
    const int lane = tid & 31;
    const int warp = tid >> 5;
    const int grp  = lane >> 2;                // groupID (0..7)
    const int tg   = lane & 3;                 // thread-in-group (0..3)

    const int wbase = blockIdx.x * PPB + warp * PWRP;   // warp's first point

    // theta uniform across the warp's 64 points (P = 65536, PWRP | P)
    const float theta = latent[wbase / P] * 10.0f;
    float sn, cs;
    sincosf(theta, &sn, &cs);                  // once per warp

    // ---- B1 fragments (built once per warp): 16 hidden tiles ----
    // padded K cols: [w0,w1,w2,0, bT,0, 0,0]   bT = w3*theta + b1 (exact fp32)
    unsigned b1f[16];
    #pragma unroll
    for (int t = 0; t < 16; ++t) {
        const int h = 8 * t + grp;
        const float4 w = reinterpret_cast<const float4*>(W1)[h];
        const float bT = fmaf(w.w, theta, b1[h]);
        float lo, hi;
        if      (tg == 0) { lo = w.x; hi = w.y; }
        else if (tg == 1) { lo = w.z; hi = 0.f; }
        else if (tg == 2) { lo = bT;  hi = 0.f; }
        else              { lo = 0.f; hi = 0.f; }
        b1f[t] = h2u(__floats2half2_rn(lo, hi));
    }

    // ---- B2 fragments (once per warp): K=128 in 8 chunks; n=grp (pad>=2 -> 0)
    unsigned b2f0[8], b2f1[8];
    #pragma unroll
    for (int u = 0; u < 8; ++u) {
        if (grp < 2) {
            const float* wr = W2 + grp * 128 + 16 * u + 2 * tg;
            b2f0[u] = h2u(__floats2half2_rn(wr[0], wr[1]));
            b2f1[u] = h2u(__floats2half2_rn(wr[8], wr[9]));
        } else {
            b2f0[u] = 0u;
            b2f1[u] = 0u;
        }
    }

    const float b20 = __ldg(b2), b21 = __ldg(b2 + 1);
    const __half2 hz = __float2half2_rn(0.0f);
    const uint32_t* sw = reinterpret_cast<const uint32_t*>(sCon);
    const int abase = (warp * 32 + grp) * 4 + tg;

    #pragma unroll 1
    for (int t = 0; t < TILES; ++t) {
        const int tp0 = wbase + t * 32;        // tile's first point
        const int p   = tp0 + lane;            // this lane's point

        // ---- load my point, stage con row: [x0,x1,x2,0, 1,0, 0,0] fp16 ----
        const float* ip = input + (size_t)p * 3;
        const float x0 = ip[0], x1 = ip[1], x2 = ip[2];
        sCon[warp * 32 + lane] =
            make_uint4(h2u(__floats2half2_rn(x0, x1)),
                       h2u(__floats2half2_rn(x2, 0.0f)),     // theta col zeroed
                       h2u(__floats2half2_rn(1.0f, 0.0f)),   // bias col = 1
                       0u);

        // ---- exact fp32 outputs: eval + con (overlaps staging latency) ----
        {
            reinterpret_cast<float4*>(out + BP)[p] = make_float4(x0, x1, x2, theta);
            const float d0 = x0 - theta, d1 = x1, d2 = x2;
            const float f1 = 1.4f * d0 * d0 + 1.4f * d1 * d1
                           + 0.2f * d2 * d2 - 0.5f;
            const float a2 = d2 + 0.4f;
            const float c20 = d0 * cs + d1 * sn, c21 = d1 * cs - d0 * sn;
            const float f2v = 3.8f * c20 * c20 + 0.6f * c21 * c21
                            + 3.8f * a2 * a2 - 0.5f;
            const float a3 = d2 - 0.6f;
            const float c30 = d0 * cs - d1 * sn, c31 = d0 * sn + d1 * cs;
            const float f3v = 0.35f * c30 * c30 + 2.8f * c31 * c31
                            + 2.8f * a3 * a3 - 0.5f;
            out[p] = fminf(f1, fminf(f2v, f3v));
        }

        __syncwarp();

        // ---- A fragments (reused by ALL 16 MMA1 tiles): 4 LDS.32 ----
        const unsigned a00 = sw[abase];            // subtile 0: rows grp, grp+8
        const unsigned a01 = sw[abase + 32];
        const unsigned a10 = sw[abase + 64];       // subtile 1: rows 16+grp, 24+grp
        const unsigned a11 = sw[abase + 96];

        __syncwarp();   // reads done before next tile overwrites the slice

        float acc0[4] = {0.f, 0.f, 0.f, 0.f};
        float acc1[4] = {0.f, 0.f, 0.f, 0.f};

        #pragma unroll
        for (int u = 0; u < 8; ++u) {
            // MMA1: hidden tiles 2u, 2u+1 for both 16-pt subtiles (f16 accum)
            unsigned d0, d1, e0, e1, f0, f1, g0, g1;
            mma8(d0, d1, a00, a01, b1f[2 * u]);
            mma8(e0, e1, a00, a01, b1f[2 * u + 1]);
            mma8(f0, f1, a10, a11, b1f[2 * u]);
            mma8(g0, g1, a10, a11, b1f[2 * u + 1]);

            // relu in registers
            d0 = h2u(__hmax2(u2h(d0), hz));  d1 = h2u(__hmax2(u2h(d1), hz));
            e0 = h2u(__hmax2(u2h(e0), hz));  e1 = h2u(__hmax2(u2h(e1), hz));
            f0 = h2u(__hmax2(u2h(f0), hz));  f1 = h2u(__hmax2(u2h(f1), hz));
            g0 = h2u(__hmax2(u2h(g0), hz));  g1 = h2u(__hmax2(u2h(g1), hz));

            // MMA2: f16 C-frag of m16n8 == A-frag halves of m16n8k16
            mma16(acc0, d0, d1, e0, e1, b2f0[u], b2f1[u]);
            mma16(acc1, f0, f1, g0, g1, b2f0[u], b2f1[u]);
        }

        // ---- epilogue: probs live on tg==0 lanes; n={0,1} ----
        if (tg == 0) {
            float2* prp = reinterpret_cast<float2*>(out + (size_t)5 * BP);
            const int q0 = tp0 + grp;
            prp[q0]      = make_float2(acc0[0] + b20, acc0[1] + b21);
            prp[q0 + 8]  = make_float2(acc0[2] + b20, acc0[3] + b21);
            prp[q0 + 16] = make_float2(acc1[0] + b20, acc1[1] + b21);
            prp[q0 + 24] = make_float2(acc1[2] + b20, acc1[3] + b21);
        }
    }
}

extern "C" void kernel_launch(void* const* d_in, const int* in_sizes, int n_in,
                              void* d_out, int out_size)
{
    const float* input  = (const float*)d_in[0];
    const float* latent = (const float*)d_in[1];
    const float* W1     = (const float*)d_in[2];
    const float* b1     = (const float*)d_in[3];
    const float* W2     = (const float*)d_in[4];
    const float* b2     = (const float*)d_in[5];
    float*       out    = (float*)d_out;

    const int BP = in_sizes[0] / 3;     // total points (B*P)
    const int B  = in_sizes[1];
    const int P  = BP / B;
    const int blocks = BP / PPB;        // 1024

    cubeflow_mma_kernel<<<blocks, TPB>>>(input, latent, W1, b1, W2, b2,
                                         out, P, BP);
}